// round 1
// baseline (speedup 1.0000x reference)
#include <cuda_runtime.h>
#include <math.h>

// ---------------------------------------------------------------------------
// Problem constants
// ---------------------------------------------------------------------------
namespace {
constexpr int Bn = 256, Sn = 128, En = 300, Pn = 200, Cn = 3;
constexpr long BS = (long)Bn * Sn;  // 32768

// scratch arena offsets (in floats)
constexpr long OFF_MASK1 = 0;
constexpr long OFF_MASK2 = OFF_MASK1 + BS;
constexpr long OFF_CAT1  = OFF_MASK2 + BS;            // [BS, 600] = [e1 | xp1]
constexpr long OFF_CAT2  = OFF_CAT1 + BS * 2 * En;    // [BS, 600]
constexpr long OFF_F     = OFF_CAT2 + BS * 2 * En;    // [BS, 300] intra F (reused per side)
constexpr long OFF_ATT   = OFF_F + BS * En;           // [B, S, S] intra attention (reused)
constexpr long OFF_CAT1P = OFF_ATT + BS * Sn;         // [BS, 400] = [x1p | beta]
constexpr long OFF_CAT2P = OFF_CAT1P + BS * 2 * Pn;   // [BS, 400] = [x2p | alpha]
constexpr long OFF_FA1   = OFF_CAT2P + BS * 2 * Pn;   // [BS, 200]
constexpr long OFF_FA2   = OFF_FA1 + BS * Pn;         // [BS, 200]
constexpr long OFF_SIM   = OFF_FA2 + BS * Pn;         // [B, S, S]
constexpr long OFF_SMT   = OFF_SIM + BS * Sn;         // [B, S, S] col-softmax, transposed
constexpr long OFF_V1    = OFF_SMT + BS * Sn;         // [BS, 400]
constexpr long OFF_V2    = OFF_V1 + BS * 2 * Pn;      // [BS, 400]
constexpr long OFF_POOL  = OFF_V2 + BS * 2 * Pn;      // [B, 800]
constexpr long TOTAL     = OFF_POOL + (long)Bn * 4 * Pn;
}  // namespace

__device__ float g_scratch[TOTAL];

// ---------------------------------------------------------------------------
// Sequence masks: mask[b,s] = (s < count_nonzero(x[b,:]))
// ---------------------------------------------------------------------------
__global__ void k_seqmask(const int* __restrict__ x1, const int* __restrict__ x2) {
    int b = blockIdx.x;
    const int* x = blockIdx.y ? x2 : x1;
    float* m = g_scratch + (blockIdx.y ? OFF_MASK2 : OFF_MASK1);
    int t = threadIdx.x;  // 0..127
    int nz = __syncthreads_count(x[b * Sn + t] != 0);
    m[b * Sn + t] = (t < nz) ? 1.0f : 0.0f;
}

// ---------------------------------------------------------------------------
// Gather + L2-normalize embedding rows into cat[:, 0:300]
// ---------------------------------------------------------------------------
__global__ void k_gather(const int* __restrict__ x1, const int* __restrict__ x2,
                         const float* __restrict__ emb) {
    long bs = blockIdx.x;
    const int* x = blockIdx.y ? x2 : x1;
    float* cat = g_scratch + (blockIdx.y ? OFF_CAT2 : OFF_CAT1);
    int row = x[bs];
    const float* e = emb + (long)row * En;
    int t = threadIdx.x;  // 128 threads
    float v[3];
    float ss = 0.f;
#pragma unroll
    for (int i = 0; i < 3; i++) {
        int idx = t + i * 128;
        v[i] = (idx < En) ? e[idx] : 0.f;
        ss += v[i] * v[i];
    }
    __shared__ float red[4];
#pragma unroll
    for (int o = 16; o; o >>= 1) ss += __shfl_xor_sync(0xffffffffu, ss, o);
    if ((t & 31) == 0) red[t >> 5] = ss;
    __syncthreads();
    float tot = red[0] + red[1] + red[2] + red[3];
    float inv = 1.0f / sqrtf(fmaxf(tot, 1e-12f));
    float* out = cat + bs * (2L * En);
#pragma unroll
    for (int i = 0; i < 3; i++) {
        int idx = t + i * 128;
        if (idx < En) out[idx] = v[i] * inv;
    }
}

// ---------------------------------------------------------------------------
// Generic batched NN GEMM: C[b] = (relu?)(A[b](MxK,lda) @ W[b](KxN,ldw))
// A/W may come from inputs (ext ptr) or the scratch arena (offset).
// Tiles: 64x64x16, 256 threads, 4x4 per thread.
// ---------------------------------------------------------------------------
__global__ void __launch_bounds__(256) k_gemm_nn(
    const float* __restrict__ Aext, long offA, int lda, long sA,
    const float* __restrict__ Wext, long offW, int ldw, long sW,
    long offC, int ldc, long sC,
    int M, int N, int K, int doRelu) {
    const float* A = (Aext ? Aext : (g_scratch + offA)) + (long)blockIdx.z * sA;
    const float* W = (Wext ? Wext : (g_scratch + offW)) + (long)blockIdx.z * sW;
    float* C = g_scratch + offC + (long)blockIdx.z * sC;

    __shared__ float As[16][64];
    __shared__ float Ws[16][64];
    int tid = threadIdx.x;
    int tx = tid & 15, ty = tid >> 4;
    int row0 = blockIdx.y * 64, col0 = blockIdx.x * 64;
    float acc[4][4] = {};

    int a_k = tid & 15, a_r = tid >> 4;  // A-load: 16 rows / pass
    int w_c = tid & 63, w_k = tid >> 6;  // W-load: 4 k / pass

    for (int k0 = 0; k0 < K; k0 += 16) {
#pragma unroll
        for (int p = 0; p < 4; p++) {
            int r = a_r + p * 16;
            int gr = row0 + r, gk = k0 + a_k;
            As[a_k][r] = (gr < M && gk < K) ? A[(long)gr * lda + gk] : 0.f;
        }
#pragma unroll
        for (int p = 0; p < 4; p++) {
            int kk = w_k + p * 4;
            int gk = k0 + kk, gc = col0 + w_c;
            Ws[kk][w_c] = (gk < K && gc < N) ? W[(long)gk * ldw + gc] : 0.f;
        }
        __syncthreads();
#pragma unroll
        for (int kk = 0; kk < 16; kk++) {
            float a[4], w[4];
#pragma unroll
            for (int i = 0; i < 4; i++) a[i] = As[kk][ty * 4 + i];
#pragma unroll
            for (int j = 0; j < 4; j++) w[j] = Ws[kk][tx * 4 + j];
#pragma unroll
            for (int i = 0; i < 4; i++)
#pragma unroll
                for (int j = 0; j < 4; j++) acc[i][j] += a[i] * w[j];
        }
        __syncthreads();
    }
#pragma unroll
    for (int i = 0; i < 4; i++) {
        int gr = row0 + ty * 4 + i;
        if (gr >= M) continue;
#pragma unroll
        for (int j = 0; j < 4; j++) {
            int gc = col0 + tx * 4 + j;
            if (gc >= N) continue;
            float v = acc[i][j];
            if (doRelu) v = fmaxf(v, 0.f);
            C[(long)gr * ldc + gc] = v;
        }
    }
}

// ---------------------------------------------------------------------------
// Batched NT GEMM: C[b](MxN) = A[b](MxK,lda) @ B[b](NxK,ldb)^T
// Optional multiplicative mask epilogue: C *= maskR[b,row]*maskC[b,col].
// ---------------------------------------------------------------------------
__global__ void __launch_bounds__(256) k_gemm_nt(
    long offA, int lda, long sA,
    long offB, int ldb, long sB,
    long offC, int ldc, long sC,
    int M, int N, int K,
    long offMaskR, long offMaskC, int useMask) {
    int b = blockIdx.z;
    const float* A = g_scratch + offA + (long)b * sA;
    const float* Bm = g_scratch + offB + (long)b * sB;
    float* C = g_scratch + offC + (long)b * sC;

    __shared__ float As[16][64];
    __shared__ float Bs[16][64];
    int tid = threadIdx.x;
    int tx = tid & 15, ty = tid >> 4;
    int row0 = blockIdx.y * 64, col0 = blockIdx.x * 64;
    float acc[4][4] = {};

    int l_k = tid & 15, l_r = tid >> 4;

    for (int k0 = 0; k0 < K; k0 += 16) {
#pragma unroll
        for (int p = 0; p < 4; p++) {
            int r = l_r + p * 16;
            int gr = row0 + r, gk = k0 + l_k;
            As[l_k][r] = (gr < M && gk < K) ? A[(long)gr * lda + gk] : 0.f;
        }
#pragma unroll
        for (int p = 0; p < 4; p++) {
            int c = l_r + p * 16;
            int gc = col0 + c, gk = k0 + l_k;
            Bs[l_k][c] = (gc < N && gk < K) ? Bm[(long)gc * ldb + gk] : 0.f;
        }
        __syncthreads();
#pragma unroll
        for (int kk = 0; kk < 16; kk++) {
            float a[4], w[4];
#pragma unroll
            for (int i = 0; i < 4; i++) a[i] = As[kk][ty * 4 + i];
#pragma unroll
            for (int j = 0; j < 4; j++) w[j] = Bs[kk][tx * 4 + j];
#pragma unroll
            for (int i = 0; i < 4; i++)
#pragma unroll
                for (int j = 0; j < 4; j++) acc[i][j] += a[i] * w[j];
        }
        __syncthreads();
    }
    const float* mR = g_scratch + offMaskR + (long)b * Sn;
    const float* mC = g_scratch + offMaskC + (long)b * Sn;
#pragma unroll
    for (int i = 0; i < 4; i++) {
        int gr = row0 + ty * 4 + i;
        if (gr >= M) continue;
        float rowm = useMask ? mR[gr] : 1.0f;
#pragma unroll
        for (int j = 0; j < 4; j++) {
            int gc = col0 + tx * 4 + j;
            if (gc >= N) continue;
            float v = acc[i][j];
            if (useMask) v *= rowm * mC[gc];
            C[(long)gr * ldc + gc] = v;
        }
    }
}

// ---------------------------------------------------------------------------
// Row softmax over last axis (S=128), in place, optional distance bias.
// grid = B*S blocks, 128 threads.
// ---------------------------------------------------------------------------
__global__ void k_softmax_rows(long off, const float* __restrict__ biasPtr, int useDbias) {
    long bi = blockIdx.x;
    int i = (int)(bi % Sn);
    float* row = g_scratch + off + bi * Sn;
    int j = threadIdx.x;
    float v = row[j];
    if (useDbias) {
        int d = i - j; if (d < 0) d = -d;
        if (d >= 10) v += biasPtr[0];
    }
    __shared__ float shm[4];
    __shared__ float shs[4];
    float m = v;
#pragma unroll
    for (int o = 16; o; o >>= 1) m = fmaxf(m, __shfl_xor_sync(0xffffffffu, m, o));
    if ((j & 31) == 0) shm[j >> 5] = m;
    __syncthreads();
    m = fmaxf(fmaxf(shm[0], shm[1]), fmaxf(shm[2], shm[3]));
    float e = expf(v - m);
    float s = e;
#pragma unroll
    for (int o = 16; o; o >>= 1) s += __shfl_xor_sync(0xffffffffu, s, o);
    if ((j & 31) == 0) shs[j >> 5] = s;
    __syncthreads();
    s = shs[0] + shs[1] + shs[2] + shs[3];
    row[j] = e / s;
}

// ---------------------------------------------------------------------------
// Column softmax written TRANSPOSED: out[b,j,k] = softmax_k(sim[b,k,j]).
// grid = (B, 4): 32 columns per block. 256 threads.
// ---------------------------------------------------------------------------
__global__ void k_softmax_colsT(long offSim, long offOut) {
    int b = blockIdx.x;
    int j0 = blockIdx.y * 32;
    __shared__ float sh[128][33];
    __shared__ float cmax[32], cinv[32];
    const float* sim = g_scratch + offSim + (long)b * Sn * Sn;
    float* outT = g_scratch + offOut + (long)b * Sn * Sn;
    int tid = threadIdx.x;
    for (int idx = tid; idx < 128 * 32; idx += 256) {
        int k = idx >> 5, j = idx & 31;
        sh[k][j] = sim[k * Sn + j0 + j];
    }
    __syncthreads();
    if (tid < 32) {
        float m = -1e30f;
        for (int k = 0; k < 128; k++) m = fmaxf(m, sh[k][tid]);
        float s = 0.f;
        for (int k = 0; k < 128; k++) s += expf(sh[k][tid] - m);
        cmax[tid] = m;
        cinv[tid] = 1.0f / s;
    }
    __syncthreads();
    for (int idx = tid; idx < 128 * 32; idx += 256) {
        int j = idx >> 7, k = idx & 127;
        outT[(long)(j0 + j) * Sn + k] = expf(sh[k][j] - cmax[j]) * cinv[j];
    }
}

// ---------------------------------------------------------------------------
// Masked-sum pooling: pool[b, 0:400] = sum_s v1*m1 ; pool[b, 400:800] = sum_s v2*m2
// ---------------------------------------------------------------------------
__global__ void k_pool() {
    int b = blockIdx.x;
    __shared__ float m1[128], m2[128];
    int tid = threadIdx.x;  // 256
    if (tid < 128) {
        m1[tid] = g_scratch[OFF_MASK1 + (long)b * Sn + tid];
        m2[tid] = g_scratch[OFF_MASK2 + (long)b * Sn + tid];
    }
    __syncthreads();
    const float* v1 = g_scratch + OFF_V1 + (long)b * Sn * 400;
    const float* v2 = g_scratch + OFF_V2 + (long)b * Sn * 400;
    float* pool = g_scratch + OFF_POOL + (long)b * 800;
    for (int n = tid; n < 400; n += 256) {
        float s1 = 0.f, s2 = 0.f;
        for (int s = 0; s < 128; s++) {
            s1 += v1[(long)s * 400 + n] * m1[s];
            s2 += v2[(long)s * 400 + n] * m2[s];
        }
        pool[n] = s1;
        pool[400 + n] = s2;
    }
}

// ---------------------------------------------------------------------------
// Final: y[b,c] = relu(pool[b,:] @ w_agg[:,c]).  grid=B, 96 threads (warp/class)
// ---------------------------------------------------------------------------
__global__ void k_final(const float* __restrict__ w_agg, float* __restrict__ out) {
    int b = blockIdx.x;
    int tid = threadIdx.x;
    int c = tid >> 5, lane = tid & 31;
    const float* p = g_scratch + OFF_POOL + (long)b * 800;
    float acc = 0.f;
    for (int n = lane; n < 800; n += 32) acc += p[n] * w_agg[n * Cn + c];
#pragma unroll
    for (int o = 16; o; o >>= 1) acc += __shfl_xor_sync(0xffffffffu, acc, o);
    if (lane == 0) out[b * Cn + c] = fmaxf(acc, 0.f);
}

// ---------------------------------------------------------------------------
// Orchestration
// ---------------------------------------------------------------------------
extern "C" void kernel_launch(void* const* d_in, const int* in_sizes, int n_in,
                              void* d_out, int out_size) {
    const int* x1 = (const int*)d_in[0];
    const int* x2 = (const int*)d_in[1];
    const float* emb = (const float*)d_in[2];
    const float* w_intra = (const float*)d_in[3];
    const float* bias_intra = (const float*)d_in[4];
    const float* w_proj1 = (const float*)d_in[5];
    const float* w_proj2 = (const float*)d_in[6];
    const float* w_att = (const float*)d_in[7];
    const float* w_cmp1 = (const float*)d_in[8];
    const float* w_cmp2 = (const float*)d_in[9];
    const float* w_agg = (const float*)d_in[10];
    float* out = (float*)d_out;

    k_seqmask<<<dim3(Bn, 2), Sn>>>(x1, x2);
    k_gather<<<dim3((unsigned)BS, 2), 128>>>(x1, x2, emb);

    for (int side = 0; side < 2; side++) {
        long offCat = side ? OFF_CAT2 : OFF_CAT1;
        long offCatP = side ? OFF_CAT2P : OFF_CAT1P;
        long offFA = side ? OFF_FA2 : OFF_FA1;
        const float* wp = side ? w_proj2 : w_proj1;

        // f = relu(e @ w_intra)   [32768 x 300] = [32768 x 300] @ [300 x 300]
        k_gemm_nn<<<dim3(5, 512, 1), 256>>>(
            nullptr, offCat, 2 * En, 0,
            w_intra, 0, En, 0,
            OFF_F, En, 0,
            (int)BS, En, En, 1);

        // att[b] = f[b] @ f[b]^T   [128 x 128], K = 300
        k_gemm_nt<<<dim3(2, 2, Bn), 256>>>(
            OFF_F, En, (long)Sn * En,
            OFF_F, En, (long)Sn * En,
            OFF_ATT, Sn, (long)Sn * Sn,
            Sn, Sn, En,
            0, 0, 0);

        // softmax(att + dbias) rows, in place
        k_softmax_rows<<<(unsigned)BS, Sn>>>(OFF_ATT, bias_intra, 1);

        // xp[b] = att[b] @ e[b]  -> cat[:, 300:600]
        k_gemm_nn<<<dim3(5, 2, Bn), 256>>>(
            nullptr, OFF_ATT, Sn, (long)Sn * Sn,
            nullptr, offCat, 2 * En, (long)Sn * 2 * En,
            offCat + En, 2 * En, (long)Sn * 2 * En,
            Sn, En, Sn, 0);

        // xp_proj = relu(cat @ w_proj)  [32768 x 200], K=600 -> catp[:, 0:200]
        k_gemm_nn<<<dim3(4, 512, 1), 256>>>(
            nullptr, offCat, 2 * En, 0,
            wp, 0, Pn, 0,
            offCatP, 2 * Pn, 0,
            (int)BS, Pn, 2 * En, 1);

        // fa = relu(xp_proj @ w_att)  [32768 x 200], K=200
        k_gemm_nn<<<dim3(4, 512, 1), 256>>>(
            nullptr, offCatP, 2 * Pn, 0,
            w_att, 0, Pn, 0,
            offFA, Pn, 0,
            (int)BS, Pn, Pn, 1);
    }

    // sim[b] = fa1[b] @ fa2[b]^T, masked multiplicatively
    k_gemm_nt<<<dim3(2, 2, Bn), 256>>>(
        OFF_FA1, Pn, (long)Sn * Pn,
        OFF_FA2, Pn, (long)Sn * Pn,
        OFF_SIM, Sn, (long)Sn * Sn,
        Sn, Sn, Pn,
        OFF_MASK1, OFF_MASK2, 1);

    // smT = softmax over axis=1, written transposed (before row softmax clobbers sim)
    k_softmax_colsT<<<dim3(Bn, 4), 256>>>(OFF_SIM, OFF_SMT);

    // sm2 = softmax over axis=2, in place
    k_softmax_rows<<<(unsigned)BS, Sn>>>(OFF_SIM, nullptr, 0);

    // beta[b] = sm2[b] @ x2p[b]  -> cat1p[:, 200:400]
    k_gemm_nn<<<dim3(4, 2, Bn), 256>>>(
        nullptr, OFF_SIM, Sn, (long)Sn * Sn,
        nullptr, OFF_CAT2P, 2 * Pn, (long)Sn * 2 * Pn,
        OFF_CAT1P + Pn, 2 * Pn, (long)Sn * 2 * Pn,
        Sn, Pn, Sn, 0);

    // alpha[b] = smT[b] @ x1p[b] -> cat2p[:, 200:400]
    k_gemm_nn<<<dim3(4, 2, Bn), 256>>>(
        nullptr, OFF_SMT, Sn, (long)Sn * Sn,
        nullptr, OFF_CAT1P, 2 * Pn, (long)Sn * 2 * Pn,
        OFF_CAT2P + Pn, 2 * Pn, (long)Sn * 2 * Pn,
        Sn, Pn, Sn, 0);

    // v1 = relu([x1p, beta] @ w_cmp1)  [32768 x 400], K=400
    k_gemm_nn<<<dim3(7, 512, 1), 256>>>(
        nullptr, OFF_CAT1P, 2 * Pn, 0,
        w_cmp1, 0, 2 * Pn, 0,
        OFF_V1, 2 * Pn, 0,
        (int)BS, 2 * Pn, 2 * Pn, 1);

    // v2 = relu([x2p, alpha] @ w_cmp2)
    k_gemm_nn<<<dim3(7, 512, 1), 256>>>(
        nullptr, OFF_CAT2P, 2 * Pn, 0,
        w_cmp2, 0, 2 * Pn, 0,
        OFF_V2, 2 * Pn, 0,
        (int)BS, 2 * Pn, 2 * Pn, 1);

    // masked sum pooling + final head
    k_pool<<<Bn, 256>>>();
    k_final<<<Bn, 96>>>(w_agg, out);
}

// round 3
// speedup vs baseline: 2.8293x; 2.8293x over previous
#include <cuda_runtime.h>
#include <cuda_bf16.h>
#include <math.h>
#include <stdint.h>

// ---------------------------------------------------------------------------
// Problem constants + scratch arena
// ---------------------------------------------------------------------------
namespace {
constexpr int Bn = 256, Sn = 128, En = 300, Pn = 200, Cn = 3;
constexpr long BS = (long)Bn * Sn;  // 32768

constexpr long OFF_MASK1 = 0;
constexpr long OFF_MASK2 = OFF_MASK1 + BS;
constexpr long OFF_CAT1  = OFF_MASK2 + BS;            // [BS, 600] = [e1 | xp1]
constexpr long OFF_CAT2  = OFF_CAT1 + BS * 2 * En;    // [BS, 600]
constexpr long OFF_F     = OFF_CAT2 + BS * 2 * En;    // [BS, 300]
constexpr long OFF_ATT   = OFF_F + BS * En;           // [B, S, S]
constexpr long OFF_CAT1P = OFF_ATT + BS * Sn;         // [BS, 400] = [x1p | beta]
constexpr long OFF_CAT2P = OFF_CAT1P + BS * 2 * Pn;   // [BS, 400] = [x2p | alpha]
constexpr long OFF_FA1   = OFF_CAT2P + BS * 2 * Pn;   // [BS, 200]
constexpr long OFF_FA2   = OFF_FA1 + BS * Pn;         // [BS, 200]
constexpr long OFF_SIM   = OFF_FA2 + BS * Pn;         // [B, S, S]
constexpr long OFF_SMT   = OFF_SIM + BS * Sn;         // [B, S, S] col-softmax transposed
constexpr long OFF_V1    = OFF_SMT + BS * Sn;         // [BS, 400]
constexpr long OFF_V2    = OFF_V1 + BS * 2 * Pn;      // [BS, 400]
constexpr long OFF_POOL  = OFF_V2 + BS * 2 * Pn;      // [B, 800]
constexpr long TOTAL     = OFF_POOL + (long)Bn * 4 * Pn;

// transposed+split weights, bf16 [N][K]; hi at off, lo at off + K*N
constexpr long WT_INTRA = 0;                        // 300x300
constexpr long WT_PROJ1 = WT_INTRA + 2L * 90000;    // 200x600
constexpr long WT_PROJ2 = WT_PROJ1 + 2L * 120000;
constexpr long WT_ATT   = WT_PROJ2 + 2L * 120000;   // 200x200
constexpr long WT_CMP1  = WT_ATT + 2L * 40000;      // 400x400
constexpr long WT_CMP2  = WT_CMP1 + 2L * 160000;
constexpr long WT_TOTAL = WT_CMP2 + 2L * 160000;

// staging smem regions (bytes): rows padded to 80B for conflict-free ldmatrix
constexpr int SM_AH = 0;
constexpr int SM_AL = 10240;
constexpr int SM_BH = 20480;
constexpr int SM_BL = 30720;
constexpr int SM_BYTES = 40960;
}  // namespace

__device__ float g_scratch[TOTAL];
__device__ __nv_bfloat16 g_wt[WT_TOTAL];

// ---------------------------------------------------------------------------
// helpers
// ---------------------------------------------------------------------------
__device__ __forceinline__ uint32_t smem_u32(const void* p) {
    uint32_t a;
    asm("{ .reg .u64 t; cvta.to.shared.u64 t, %1; cvt.u32.u64 %0, t; }" : "=r"(a) : "l"(p));
    return a;
}
__device__ __forceinline__ uint32_t packbf(__nv_bfloat16 a, __nv_bfloat16 b) {
    __nv_bfloat162 t;
    t.x = a; t.y = b;
    return *reinterpret_cast<uint32_t*>(&t);
}
__device__ __forceinline__ void split2(float2 v, uint32_t& hp, uint32_t& lp) {
    __nv_bfloat16 hx = __float2bfloat16(v.x), hy = __float2bfloat16(v.y);
    __nv_bfloat16 lx = __float2bfloat16(v.x - __bfloat162float(hx));
    __nv_bfloat16 ly = __float2bfloat16(v.y - __bfloat162float(hy));
    hp = packbf(hx, hy);
    lp = packbf(lx, ly);
}
__device__ __forceinline__ void split1(float v, __nv_bfloat16& h, __nv_bfloat16& l) {
    h = __float2bfloat16(v);
    l = __float2bfloat16(v - __bfloat162float(h));
}

__device__ __forceinline__ void ldm_x4(uint32_t* r, uint32_t addr) {
    asm volatile("ldmatrix.sync.aligned.m8n8.x4.shared.b16 {%0,%1,%2,%3}, [%4];"
                 : "=r"(r[0]), "=r"(r[1]), "=r"(r[2]), "=r"(r[3]) : "r"(addr));
}
__device__ __forceinline__ void ldm_x2(uint32_t* r, uint32_t addr) {
    asm volatile("ldmatrix.sync.aligned.m8n8.x2.shared.b16 {%0,%1}, [%2];"
                 : "=r"(r[0]), "=r"(r[1]) : "r"(addr));
}
__device__ __forceinline__ void mma16816(float* c, const uint32_t* a, const uint32_t* b) {
    asm volatile(
        "mma.sync.aligned.m16n8k16.row.col.f32.bf16.bf16.f32 "
        "{%0,%1,%2,%3}, {%4,%5,%6,%7}, {%8,%9}, {%0,%1,%2,%3};"
        : "+f"(c[0]), "+f"(c[1]), "+f"(c[2]), "+f"(c[3])
        : "r"(a[0]), "r"(a[1]), "r"(a[2]), "r"(a[3]), "r"(b[0]), "r"(b[1]));
}

// ---------------------------------------------------------------------------
// Universal HMMA GEMM with bf16 two-term split (3 MMAs per k-step).
//   C[b](M x Nreal) (+relu/+mask) = A[b](f32 [M][K], row stride lda) @ B^T
//   B: weights at g_wt+wtOff ([Nreal][K] bf16, lo at +K*Nreal), or f32
//      activations: bNmajor=0 -> [N][K] (K contiguous); 1 -> [K][N].
//   grid = (ceil(Nreal/128), M/128, batch); 256 threads.
// ---------------------------------------------------------------------------
__global__ void __launch_bounds__(256, 2)
k_hmma_gemm(long offA, int lda, long sA,
            long wtOff,
            long offB, int ldb, long sB, int bNmajor,
            long offC, int ldc, long sC,
            int Nreal, int K,
            int doRelu, int useMask, long offMaskR, long offMaskC) {
    __shared__ __align__(16) char sm[SM_BYTES];
    const uint32_t sb = smem_u32(sm);
    const int tid = threadIdx.x;
    const int lane = tid & 31, wid = tid >> 5;
    const int wm = wid & 1, wn = wid >> 1;  // 2 x 4 warp grid -> 64x32 per warp
    const int n0 = blockIdx.x * 128, m0 = blockIdx.y * 128, b = blockIdx.z;

    const float* A = g_scratch + offA + (long)b * sA;
    const float* Bf = g_scratch + offB + (long)b * sB;
    float* C = g_scratch + offC + (long)b * sC;
    const bool useWt = (wtOff >= 0);
    const __nv_bfloat16* WtHi = g_wt + (useWt ? wtOff : 0);
    const __nv_bfloat16* WtLo = WtHi + (long)K * Nreal;

    float acc[4][4][4] = {};

    const int kp = tid & 15, srow = tid >> 4;  // staging coords (K-major paths)

    const int nChunks = (K + 31) >> 5;
    for (int c = 0; c < nChunks; c++) {
        const int k0 = c << 5;
        // ---- stage A: 128 rows x 32 k, f32 -> bf16 hi/lo
        {
            const int gk = k0 + kp * 2;
            const bool kin = (gk < K);
#pragma unroll
            for (int it = 0; it < 8; it++) {
                int row = srow + it * 16;
                float2 v = kin ? *reinterpret_cast<const float2*>(A + (long)(m0 + row) * lda + gk)
                               : make_float2(0.f, 0.f);
                uint32_t hp, lp;
                split2(v, hp, lp);
                *reinterpret_cast<uint32_t*>(sm + SM_AH + row * 80 + kp * 4) = hp;
                *reinterpret_cast<uint32_t*>(sm + SM_AL + row * 80 + kp * 4) = lp;
            }
        }
        // ---- stage B
        if (useWt) {
            const int gk = k0 + kp * 2;
            const bool kin = (gk < K);
#pragma unroll
            for (int it = 0; it < 8; it++) {
                int n = srow + it * 16;
                int gn = n0 + n;
                uint32_t hp = 0, lp = 0;
                if (kin && gn < Nreal) {
                    long e = (long)gn * K + gk;
                    hp = *reinterpret_cast<const uint32_t*>(WtHi + e);
                    lp = *reinterpret_cast<const uint32_t*>(WtLo + e);
                }
                *reinterpret_cast<uint32_t*>(sm + SM_BH + n * 80 + kp * 4) = hp;
                *reinterpret_cast<uint32_t*>(sm + SM_BL + n * 80 + kp * 4) = lp;
            }
        } else if (!bNmajor) {  // activation B, [N][K]
            const int gk = k0 + kp * 2;
            const bool kin = (gk < K);
#pragma unroll
            for (int it = 0; it < 8; it++) {
                int n = srow + it * 16;
                int gn = n0 + n;
                float2 v = (kin && gn < Nreal)
                               ? *reinterpret_cast<const float2*>(Bf + (long)gn * ldb + gk)
                               : make_float2(0.f, 0.f);
                uint32_t hp, lp;
                split2(v, hp, lp);
                *reinterpret_cast<uint32_t*>(sm + SM_BH + n * 80 + kp * 4) = hp;
                *reinterpret_cast<uint32_t*>(sm + SM_BL + n * 80 + kp * 4) = lp;
            }
        } else {  // activation B, [K][N] (N contiguous) -> transpose into smem
            const int n = (tid & 63) * 2;
            const int kb = tid >> 6;
            const int gn = n0 + n;
#pragma unroll
            for (int it = 0; it < 8; it++) {
                int kk = kb + it * 4;
                int gk = k0 + kk;
                float2 v = (gk < K && gn < Nreal)
                               ? *reinterpret_cast<const float2*>(Bf + (long)gk * ldb + gn)
                               : make_float2(0.f, 0.f);
                __nv_bfloat16 hx, lx, hy, ly;
                split1(v.x, hx, lx);
                split1(v.y, hy, ly);
                *reinterpret_cast<__nv_bfloat16*>(sm + SM_BH + n * 80 + kk * 2) = hx;
                *reinterpret_cast<__nv_bfloat16*>(sm + SM_BL + n * 80 + kk * 2) = lx;
                *reinterpret_cast<__nv_bfloat16*>(sm + SM_BH + (n + 1) * 80 + kk * 2) = hy;
                *reinterpret_cast<__nv_bfloat16*>(sm + SM_BL + (n + 1) * 80 + kk * 2) = ly;
            }
        }
        __syncthreads();

        // ---- compute: 2 k-steps of 16
#pragma unroll
        for (int ks = 0; ks < 2; ks++) {
            uint32_t bh[4][2], bl[4][2];
#pragma unroll
            for (int ni = 0; ni < 4; ni++) {
                uint32_t off = (uint32_t)((wn * 32 + ni * 8 + (lane & 7)) * 80 + ks * 32 +
                                          ((lane >> 3) & 1) * 16);
                ldm_x2(bh[ni], sb + SM_BH + off);
                ldm_x2(bl[ni], sb + SM_BL + off);
            }
#pragma unroll
            for (int mi = 0; mi < 4; mi++) {
                uint32_t ah[4], al[4];
                uint32_t off = (uint32_t)((wm * 64 + mi * 16 + (lane & 15)) * 80 + ks * 32 +
                                          (lane >> 4) * 16);
                ldm_x4(ah, sb + SM_AH + off);
                ldm_x4(al, sb + SM_AL + off);
#pragma unroll
                for (int ni = 0; ni < 4; ni++) {
                    mma16816(acc[mi][ni], ah, bh[ni]);
                    mma16816(acc[mi][ni], ah, bl[ni]);
                    mma16816(acc[mi][ni], al, bh[ni]);
                }
            }
        }
        __syncthreads();
    }

    // ---- epilogue: direct stores with relu / multiplicative mask
    const float* mR = g_scratch + offMaskR + (long)b * Sn;
    const float* mC = g_scratch + offMaskC + (long)b * Sn;
    const int trow = lane >> 2, tcol = (lane & 3) * 2;
#pragma unroll
    for (int mi = 0; mi < 4; mi++) {
        int r0 = m0 + wm * 64 + mi * 16 + trow;
        float rm0 = useMask ? mR[r0 - m0 + 0] : 1.0f;   // masks only used when M==Sn, m0==0
        float rm1 = useMask ? mR[r0 - m0 + 8] : 1.0f;
#pragma unroll
        for (int ni = 0; ni < 4; ni++) {
            int c0 = n0 + wn * 32 + ni * 8 + tcol;
            if (c0 >= Nreal) continue;
            float cm0 = useMask ? mC[c0] : 1.0f;
            float cm1 = useMask ? mC[c0 + 1] : 1.0f;
            float v0 = acc[mi][ni][0], v1 = acc[mi][ni][1];
            float v2 = acc[mi][ni][2], v3 = acc[mi][ni][3];
            if (doRelu) {
                v0 = fmaxf(v0, 0.f); v1 = fmaxf(v1, 0.f);
                v2 = fmaxf(v2, 0.f); v3 = fmaxf(v3, 0.f);
            }
            if (useMask) {
                v0 *= rm0 * cm0; v1 *= rm0 * cm1;
                v2 *= rm1 * cm0; v3 *= rm1 * cm1;
            }
            *reinterpret_cast<float2*>(C + (long)r0 * ldc + c0) = make_float2(v0, v1);
            *reinterpret_cast<float2*>(C + (long)(r0 + 8) * ldc + c0) = make_float2(v2, v3);
        }
    }
}

// ---------------------------------------------------------------------------
// Weight transpose + bf16 split: W [K][N] f32 -> Wt hi/lo [N][K] bf16
// ---------------------------------------------------------------------------
__global__ void k_wsplit(const float* __restrict__ W, int K, int N, long wtOff) {
    long total = (long)K * N;
    long i = (long)blockIdx.x * blockDim.x + threadIdx.x;
    if (i >= total) return;
    int n = (int)(i / K), k = (int)(i % K);
    float v = W[(long)k * N + n];
    __nv_bfloat16 h, l;
    split1(v, h, l);
    g_wt[wtOff + i] = h;
    g_wt[wtOff + total + i] = l;
}

// ---------------------------------------------------------------------------
// Non-GEMM kernels (validated in R1)
// ---------------------------------------------------------------------------
__global__ void k_seqmask(const int* __restrict__ x1, const int* __restrict__ x2) {
    int b = blockIdx.x;
    const int* x = blockIdx.y ? x2 : x1;
    float* m = g_scratch + (blockIdx.y ? OFF_MASK2 : OFF_MASK1);
    int t = threadIdx.x;
    int nz = __syncthreads_count(x[b * Sn + t] != 0);
    m[b * Sn + t] = (t < nz) ? 1.0f : 0.0f;
}

__global__ void k_gather(const int* __restrict__ x1, const int* __restrict__ x2,
                         const float* __restrict__ emb) {
    long bs = blockIdx.x;
    const int* x = blockIdx.y ? x2 : x1;
    float* cat = g_scratch + (blockIdx.y ? OFF_CAT2 : OFF_CAT1);
    int row = x[bs];
    const float* e = emb + (long)row * En;
    int t = threadIdx.x;
    float v[3];
    float ss = 0.f;
#pragma unroll
    for (int i = 0; i < 3; i++) {
        int idx = t + i * 128;
        v[i] = (idx < En) ? e[idx] : 0.f;
        ss += v[i] * v[i];
    }
    __shared__ float red[4];
#pragma unroll
    for (int o = 16; o; o >>= 1) ss += __shfl_xor_sync(0xffffffffu, ss, o);
    if ((t & 31) == 0) red[t >> 5] = ss;
    __syncthreads();
    float tot = red[0] + red[1] + red[2] + red[3];
    float inv = 1.0f / sqrtf(fmaxf(tot, 1e-12f));
    float* out = cat + bs * (2L * En);
#pragma unroll
    for (int i = 0; i < 3; i++) {
        int idx = t + i * 128;
        if (idx < En) out[idx] = v[i] * inv;
    }
}

__global__ void k_softmax_rows(long off, const float* __restrict__ biasPtr, int useDbias) {
    long bi = blockIdx.x;
    int i = (int)(bi % Sn);
    float* row = g_scratch + off + bi * Sn;
    int j = threadIdx.x;
    float v = row[j];
    if (useDbias) {
        int d = i - j; if (d < 0) d = -d;
        if (d >= 10) v += biasPtr[0];
    }
    __shared__ float shm[4];
    __shared__ float shs[4];
    float m = v;
#pragma unroll
    for (int o = 16; o; o >>= 1) m = fmaxf(m, __shfl_xor_sync(0xffffffffu, m, o));
    if ((j & 31) == 0) shm[j >> 5] = m;
    __syncthreads();
    m = fmaxf(fmaxf(shm[0], shm[1]), fmaxf(shm[2], shm[3]));
    float e = expf(v - m);
    float s = e;
#pragma unroll
    for (int o = 16; o; o >>= 1) s += __shfl_xor_sync(0xffffffffu, s, o);
    if ((j & 31) == 0) shs[j >> 5] = s;
    __syncthreads();
    s = shs[0] + shs[1] + shs[2] + shs[3];
    row[j] = e / s;
}

__global__ void k_softmax_colsT(long offSim, long offOut) {
    int b = blockIdx.x;
    int j0 = blockIdx.y * 32;
    __shared__ float sh[128][33];
    __shared__ float cmax[32], cinv[32];
    const float* sim = g_scratch + offSim + (long)b * Sn * Sn;
    float* outT = g_scratch + offOut + (long)b * Sn * Sn;
    int tid = threadIdx.x;
    for (int idx = tid; idx < 128 * 32; idx += 256) {
        int k = idx >> 5, j = idx & 31;
        sh[k][j] = sim[k * Sn + j0 + j];
    }
    __syncthreads();
    if (tid < 32) {
        float m = -1e30f;
        for (int k = 0; k < 128; k++) m = fmaxf(m, sh[k][tid]);
        float s = 0.f;
        for (int k = 0; k < 128; k++) s += expf(sh[k][tid] - m);
        cmax[tid] = m;
        cinv[tid] = 1.0f / s;
    }
    __syncthreads();
    for (int idx = tid; idx < 128 * 32; idx += 256) {
        int j = idx >> 7, k = idx & 127;
        outT[(long)(j0 + j) * Sn + k] = expf(sh[k][j] - cmax[j]) * cinv[j];
    }
}

__global__ void k_pool() {
    int b = blockIdx.x;
    __shared__ float m1[128], m2[128];
    int tid = threadIdx.x;
    if (tid < 128) {
        m1[tid] = g_scratch[OFF_MASK1 + (long)b * Sn + tid];
        m2[tid] = g_scratch[OFF_MASK2 + (long)b * Sn + tid];
    }
    __syncthreads();
    const float* v1 = g_scratch + OFF_V1 + (long)b * Sn * 400;
    const float* v2 = g_scratch + OFF_V2 + (long)b * Sn * 400;
    float* pool = g_scratch + OFF_POOL + (long)b * 800;
    for (int n = tid; n < 400; n += 256) {
        float s1 = 0.f, s2 = 0.f;
        for (int s = 0; s < 128; s++) {
            s1 += v1[(long)s * 400 + n] * m1[s];
            s2 += v2[(long)s * 400 + n] * m2[s];
        }
        pool[n] = s1;
        pool[400 + n] = s2;
    }
}

__global__ void k_final(const float* __restrict__ w_agg, float* __restrict__ out) {
    int b = blockIdx.x;
    int tid = threadIdx.x;
    int c = tid >> 5, lane = tid & 31;
    const float* p = g_scratch + OFF_POOL + (long)b * 800;
    float acc = 0.f;
    for (int n = lane; n < 800; n += 32) acc += p[n] * w_agg[n * Cn + c];
#pragma unroll
    for (int o = 16; o; o >>= 1) acc += __shfl_xor_sync(0xffffffffu, acc, o);
    if (lane == 0) out[b * Cn + c] = fmaxf(acc, 0.f);
}

// ---------------------------------------------------------------------------
// Orchestration
// ---------------------------------------------------------------------------
static inline void launch_gemm(long offA, int lda, long sA,
                               long wtOff,
                               long offB, int ldb, long sB, int bNmajor,
                               long offC, int ldc, long sC,
                               int M, int Nreal, int K,
                               int doRelu, int useMask, long offMaskR, long offMaskC,
                               int batch) {
    dim3 grid((Nreal + 127) / 128, M / 128, batch);
    k_hmma_gemm<<<grid, 256>>>(offA, lda, sA, wtOff, offB, ldb, sB, bNmajor,
                               offC, ldc, sC, Nreal, K,
                               doRelu, useMask, offMaskR, offMaskC);
}

extern "C" void kernel_launch(void* const* d_in, const int* in_sizes, int n_in,
                              void* d_out, int out_size) {
    const int* x1 = (const int*)d_in[0];
    const int* x2 = (const int*)d_in[1];
    const float* emb = (const float*)d_in[2];
    const float* w_intra = (const float*)d_in[3];
    const float* bias_intra = (const float*)d_in[4];
    const float* w_proj1 = (const float*)d_in[5];
    const float* w_proj2 = (const float*)d_in[6];
    const float* w_att = (const float*)d_in[7];
    const float* w_cmp1 = (const float*)d_in[8];
    const float* w_cmp2 = (const float*)d_in[9];
    const float* w_agg = (const float*)d_in[10];
    float* out = (float*)d_out;

    k_seqmask<<<dim3(Bn, 2), Sn>>>(x1, x2);
    k_gather<<<dim3((unsigned)BS, 2), 128>>>(x1, x2, emb);

    // split + transpose weights to bf16 hi/lo [N][K]
    k_wsplit<<<(90000 + 255) / 256, 256>>>(w_intra, En, En, WT_INTRA);
    k_wsplit<<<(120000 + 255) / 256, 256>>>(w_proj1, 2 * En, Pn, WT_PROJ1);
    k_wsplit<<<(120000 + 255) / 256, 256>>>(w_proj2, 2 * En, Pn, WT_PROJ2);
    k_wsplit<<<(40000 + 255) / 256, 256>>>(w_att, Pn, Pn, WT_ATT);
    k_wsplit<<<(160000 + 255) / 256, 256>>>(w_cmp1, 2 * Pn, 2 * Pn, WT_CMP1);
    k_wsplit<<<(160000 + 255) / 256, 256>>>(w_cmp2, 2 * Pn, 2 * Pn, WT_CMP2);

    for (int side = 0; side < 2; side++) {
        long offCat = side ? OFF_CAT2 : OFF_CAT1;
        long offCatP = side ? OFF_CAT2P : OFF_CAT1P;
        long offFA = side ? OFF_FA2 : OFF_FA1;
        long wtProj = side ? WT_PROJ2 : WT_PROJ1;

        // f = relu(e @ w_intra): [32768 x 300], K=300
        launch_gemm(offCat, 2 * En, 0, WT_INTRA, 0, 0, 0, 0,
                    OFF_F, En, 0, (int)BS, En, En, 1, 0, 0, 0, 1);

        // att[b] = f[b] @ f[b]^T: [128 x 128], K=300
        launch_gemm(OFF_F, En, (long)Sn * En, -1,
                    OFF_F, En, (long)Sn * En, 0,
                    OFF_ATT, Sn, (long)Sn * Sn, Sn, Sn, En, 0, 0, 0, 0, Bn);

        k_softmax_rows<<<(unsigned)BS, Sn>>>(OFF_ATT, bias_intra, 1);

        // xp[b] = att[b] @ e[b]: [128 x 300], K=128 (B N-major) -> cat[:,300:600]
        launch_gemm(OFF_ATT, Sn, (long)Sn * Sn, -1,
                    offCat, 2 * En, (long)Sn * 2 * En, 1,
                    offCat + En, 2 * En, (long)Sn * 2 * En, Sn, En, Sn, 0, 0, 0, 0, Bn);

        // x_proj = relu(cat @ w_proj): [32768 x 200], K=600 -> catp[:,0:200]
        launch_gemm(offCat, 2 * En, 0, wtProj, 0, 0, 0, 0,
                    offCatP, 2 * Pn, 0, (int)BS, Pn, 2 * En, 1, 0, 0, 0, 1);

        // fa = relu(x_proj @ w_att): [32768 x 200], K=200
        launch_gemm(offCatP, 2 * Pn, 0, WT_ATT, 0, 0, 0, 0,
                    offFA, Pn, 0, (int)BS, Pn, Pn, 1, 0, 0, 0, 1);
    }

    // sim[b] = fa1[b] @ fa2[b]^T, multiplicative mask epilogue
    launch_gemm(OFF_FA1, Pn, (long)Sn * Pn, -1,
                OFF_FA2, Pn, (long)Sn * Pn, 0,
                OFF_SIM, Sn, (long)Sn * Sn, Sn, Sn, Pn, 0, 1, OFF_MASK1, OFF_MASK2, Bn);

    k_softmax_colsT<<<dim3(Bn, 4), 256>>>(OFF_SIM, OFF_SMT);
    k_softmax_rows<<<(unsigned)BS, Sn>>>(OFF_SIM, nullptr, 0);

    // beta[b] = sm2[b] @ x2p[b]: [128 x 200], K=128 (B N-major) -> cat1p[:,200:400]
    launch_gemm(OFF_SIM, Sn, (long)Sn * Sn, -1,
                OFF_CAT2P, 2 * Pn, (long)Sn * 2 * Pn, 1,
                OFF_CAT1P + Pn, 2 * Pn, (long)Sn * 2 * Pn, Sn, Pn, Sn, 0, 0, 0, 0, Bn);

    // alpha[b] = smT[b] @ x1p[b] -> cat2p[:,200:400]
    launch_gemm(OFF_SMT, Sn, (long)Sn * Sn, -1,
                OFF_CAT1P, 2 * Pn, (long)Sn * 2 * Pn, 1,
                OFF_CAT2P + Pn, 2 * Pn, (long)Sn * 2 * Pn, Sn, Pn, Sn, 0, 0, 0, 0, Bn);

    // v1 = relu([x1p|beta] @ w_cmp1): [32768 x 400], K=400
    launch_gemm(OFF_CAT1P, 2 * Pn, 0, WT_CMP1, 0, 0, 0, 0,
                OFF_V1, 2 * Pn, 0, (int)BS, 2 * Pn, 2 * Pn, 1, 0, 0, 0, 1);
    // v2 = relu([x2p|alpha] @ w_cmp2)
    launch_gemm(OFF_CAT2P, 2 * Pn, 0, WT_CMP2, 0, 0, 0, 0,
                OFF_V2, 2 * Pn, 0, (int)BS, 2 * Pn, 2 * Pn, 1, 0, 0, 0, 1);

    k_pool<<<Bn, 256>>>();
    k_final<<<Bn, 96>>>(w_agg, out);
}

// round 4
// speedup vs baseline: 3.0903x; 1.0922x over previous
#include <cuda_runtime.h>
#include <cuda_bf16.h>
#include <math.h>
#include <stdint.h>

// ---------------------------------------------------------------------------
// Problem constants + scratch arena
// ---------------------------------------------------------------------------
namespace {
constexpr int Bn = 256, Sn = 128, En = 300, Pn = 200, Cn = 3;
constexpr long BS = (long)Bn * Sn;  // 32768

// sides stored contiguously where batched launches need constant stride
constexpr long OFF_MASK1 = 0;
constexpr long OFF_MASK2 = OFF_MASK1 + BS;
constexpr long OFF_CAT1  = OFF_MASK2 + BS;            // [BS,600] side1 = [e1|xp1]
constexpr long OFF_CAT2  = OFF_CAT1 + BS * 2 * En;    // [BS,600] side2 (contig)
constexpr long OFF_F     = OFF_CAT2 + BS * 2 * En;    // [2*BS,300] both sides
constexpr long OFF_ATT   = OFF_F + 2 * BS * En;       // [2*B,S,S]
constexpr long OFF_CAT1P = OFF_ATT + 2 * BS * Sn;     // [BS,400] = [x1p|beta]
constexpr long OFF_CAT2P = OFF_CAT1P + BS * 2 * Pn;   // [BS,400] = [x2p|alpha]
constexpr long OFF_FA1   = OFF_CAT2P + BS * 2 * Pn;   // [BS,200]
constexpr long OFF_FA2   = OFF_FA1 + BS * Pn;         // [BS,200]
constexpr long OFF_SIM   = OFF_FA2 + BS * Pn;         // [B,S,S]
constexpr long OFF_SMT   = OFF_SIM + BS * Sn;         // [B,S,S] col-softmax^T
constexpr long OFF_V1    = OFF_SMT + BS * Sn;         // [BS,400]
constexpr long OFF_V2    = OFF_V1 + BS * 2 * Pn;      // [BS,400]
constexpr long OFF_POOL  = OFF_V2 + BS * 2 * Pn;      // [B,800]
constexpr long TOTAL     = OFF_POOL + (long)Bn * 4 * Pn;

// transposed+split weights, bf16 [N][K]; hi at off, lo at off + K*N
constexpr long WT_INTRA = 0;                        // 300x300
constexpr long WT_PROJ1 = WT_INTRA + 2L * 90000;    // 200x600
constexpr long WT_PROJ2 = WT_PROJ1 + 2L * 120000;
constexpr long WT_ATT   = WT_PROJ2 + 2L * 120000;   // 200x200
constexpr long WT_CMP1  = WT_ATT + 2L * 40000;      // 400x400
constexpr long WT_CMP2  = WT_CMP1 + 2L * 160000;
constexpr long WT_TOTAL = WT_CMP2 + 2L * 160000;

// staging smem regions (bytes): rows padded to 80B for conflict-free ldmatrix
constexpr int SM_AH = 0;
constexpr int SM_AL = 10240;
constexpr int SM_BH = 20480;
constexpr int SM_BL = 30720;
constexpr int SM_BUF = 40960;           // one pipeline buffer
constexpr int SMEM_BYTES = 2 * SM_BUF;  // 81920 (dynamic, opt-in)
}  // namespace

__device__ float g_scratch[TOTAL];
__device__ __nv_bfloat16 g_wt[WT_TOTAL];

// ---------------------------------------------------------------------------
// helpers
// ---------------------------------------------------------------------------
__device__ __forceinline__ uint32_t smem_u32(const void* p) {
    uint32_t a;
    asm("{ .reg .u64 t; cvta.to.shared.u64 t, %1; cvt.u32.u64 %0, t; }" : "=r"(a) : "l"(p));
    return a;
}
__device__ __forceinline__ uint32_t packbf(__nv_bfloat16 a, __nv_bfloat16 b) {
    __nv_bfloat162 t;
    t.x = a; t.y = b;
    return *reinterpret_cast<uint32_t*>(&t);
}
__device__ __forceinline__ void split2(float2 v, uint32_t& hp, uint32_t& lp) {
    __nv_bfloat16 hx = __float2bfloat16(v.x), hy = __float2bfloat16(v.y);
    __nv_bfloat16 lx = __float2bfloat16(v.x - __bfloat162float(hx));
    __nv_bfloat16 ly = __float2bfloat16(v.y - __bfloat162float(hy));
    hp = packbf(hx, hy);
    lp = packbf(lx, ly);
}
__device__ __forceinline__ void split1(float v, __nv_bfloat16& h, __nv_bfloat16& l) {
    h = __float2bfloat16(v);
    l = __float2bfloat16(v - __bfloat162float(h));
}
__device__ __forceinline__ void ldm_x4(uint32_t* r, uint32_t addr) {
    asm volatile("ldmatrix.sync.aligned.m8n8.x4.shared.b16 {%0,%1,%2,%3}, [%4];"
                 : "=r"(r[0]), "=r"(r[1]), "=r"(r[2]), "=r"(r[3]) : "r"(addr));
}
__device__ __forceinline__ void ldm_x2(uint32_t* r, uint32_t addr) {
    asm volatile("ldmatrix.sync.aligned.m8n8.x2.shared.b16 {%0,%1}, [%2];"
                 : "=r"(r[0]), "=r"(r[1]) : "r"(addr));
}
__device__ __forceinline__ void mma16816(float* c, const uint32_t* a, const uint32_t* b) {
    asm volatile(
        "mma.sync.aligned.m16n8k16.row.col.f32.bf16.bf16.f32 "
        "{%0,%1,%2,%3}, {%4,%5,%6,%7}, {%8,%9}, {%0,%1,%2,%3};"
        : "+f"(c[0]), "+f"(c[1]), "+f"(c[2]), "+f"(c[3])
        : "r"(a[0]), "r"(a[1]), "r"(a[2]), "r"(a[3]), "r"(b[0]), "r"(b[1]));
}

// ---------------------------------------------------------------------------
// Pipelined HMMA GEMM, bf16 two-term split (3 MMAs / k-step).
//   C[b](M x Nreal) (+relu/+mask) = A[b](f32 [M][K], lda) @ B^T
//   B: weights at g_wt + wtOff + b*wtStride ([Nreal][K] bf16, lo at +K*N), or
//      f32 activations: bNmajor=0 -> [N][K]; 1 -> [K][N].
//   grid = (ceil(Nreal/128), M/128, batch); 256 threads; dyn smem 80KB.
// ---------------------------------------------------------------------------
__global__ void __launch_bounds__(256, 2)
k_hmma_gemm(long offA, int lda, long sA,
            long wtOff, long wtStride,
            long offB, int ldb, long sB, int bNmajor,
            long offC, int ldc, long sC,
            int Nreal, int K,
            int doRelu, int useMask, long offMaskR, long offMaskC) {
    extern __shared__ __align__(16) char smem[];
    const uint32_t sb0 = smem_u32(smem);
    const int tid = threadIdx.x;
    const int lane = tid & 31, wid = tid >> 5;
    const int wm = wid & 1, wn = wid >> 1;  // 2 x 4 warp grid -> 64x32 per warp
    const int n0 = blockIdx.x * 128, m0 = blockIdx.y * 128, b = blockIdx.z;

    const float* A = g_scratch + offA + (long)b * sA;
    const float* Bf = g_scratch + offB + (long)b * sB;
    float* C = g_scratch + offC + (long)b * sC;
    const bool useWt = (wtOff >= 0);
    const __nv_bfloat16* WtHi = g_wt + (useWt ? wtOff + (long)b * wtStride : 0);
    const __nv_bfloat16* WtLo = WtHi + (long)K * Nreal;

    float acc[4][4][4] = {};
    const int kp = tid & 15, srow = tid >> 4;
    const int nN = (tid & 63) * 2, nKb = tid >> 6;  // N-major staging coords
    const int nChunks = (K + 31) >> 5;

    float2 pfA[8], pfB[8];

// ---- prefetch chunk `c` gmem data into registers
#define PREFETCH(c)                                                              \
    {                                                                            \
        const int k0 = (c) << 5;                                                 \
        const int gk = k0 + kp * 2;                                              \
        const bool kin = (gk < K);                                               \
        _Pragma("unroll") for (int it = 0; it < 8; it++) {                       \
            int row = srow + it * 16;                                            \
            pfA[it] = kin ? *reinterpret_cast<const float2*>(                    \
                                A + (long)(m0 + row) * lda + gk)                 \
                          : make_float2(0.f, 0.f);                               \
        }                                                                        \
        if (useWt) {                                                             \
            _Pragma("unroll") for (int it = 0; it < 8; it++) {                   \
                int gn = n0 + srow + it * 16;                                    \
                uint32_t hp = 0, lp = 0;                                         \
                if (kin && gn < Nreal) {                                         \
                    long e = (long)gn * K + gk;                                  \
                    hp = *reinterpret_cast<const uint32_t*>(WtHi + e);           \
                    lp = *reinterpret_cast<const uint32_t*>(WtLo + e);           \
                }                                                                \
                pfB[it].x = __uint_as_float(hp);                                 \
                pfB[it].y = __uint_as_float(lp);                                 \
            }                                                                    \
        } else if (!bNmajor) {                                                   \
            _Pragma("unroll") for (int it = 0; it < 8; it++) {                   \
                int gn = n0 + srow + it * 16;                                    \
                pfB[it] = (kin && gn < Nreal)                                    \
                              ? *reinterpret_cast<const float2*>(                \
                                    Bf + (long)gn * ldb + gk)                    \
                              : make_float2(0.f, 0.f);                           \
            }                                                                    \
        } else {                                                                 \
            const int gn = n0 + nN;                                              \
            _Pragma("unroll") for (int it = 0; it < 8; it++) {                   \
                int gkk = k0 + nKb + it * 4;                                     \
                pfB[it] = (gkk < K && gn < Nreal)                                \
                              ? *reinterpret_cast<const float2*>(                \
                                    Bf + (long)gkk * ldb + gn)                   \
                              : make_float2(0.f, 0.f);                           \
            }                                                                    \
        }                                                                        \
    }

// ---- convert + store prefetched registers into smem buffer `bi`
#define STAGE(bi)                                                                \
    {                                                                            \
        char* sm = smem + (bi)*SM_BUF;                                           \
        _Pragma("unroll") for (int it = 0; it < 8; it++) {                       \
            int row = srow + it * 16;                                            \
            uint32_t hp, lp;                                                     \
            split2(pfA[it], hp, lp);                                             \
            *reinterpret_cast<uint32_t*>(sm + SM_AH + row * 80 + kp * 4) = hp;   \
            *reinterpret_cast<uint32_t*>(sm + SM_AL + row * 80 + kp * 4) = lp;   \
        }                                                                        \
        if (useWt) {                                                             \
            _Pragma("unroll") for (int it = 0; it < 8; it++) {                   \
                int n = srow + it * 16;                                          \
                *reinterpret_cast<uint32_t*>(sm + SM_BH + n * 80 + kp * 4) =     \
                    __float_as_uint(pfB[it].x);                                  \
                *reinterpret_cast<uint32_t*>(sm + SM_BL + n * 80 + kp * 4) =     \
                    __float_as_uint(pfB[it].y);                                  \
            }                                                                    \
        } else if (!bNmajor) {                                                   \
            _Pragma("unroll") for (int it = 0; it < 8; it++) {                   \
                int n = srow + it * 16;                                          \
                uint32_t hp, lp;                                                 \
                split2(pfB[it], hp, lp);                                         \
                *reinterpret_cast<uint32_t*>(sm + SM_BH + n * 80 + kp * 4) = hp; \
                *reinterpret_cast<uint32_t*>(sm + SM_BL + n * 80 + kp * 4) = lp; \
            }                                                                    \
        } else {                                                                 \
            _Pragma("unroll") for (int it = 0; it < 8; it++) {                   \
                int kk = nKb + it * 4;                                           \
                __nv_bfloat16 hx, lx, hy, ly;                                    \
                split1(pfB[it].x, hx, lx);                                       \
                split1(pfB[it].y, hy, ly);                                       \
                *reinterpret_cast<__nv_bfloat16*>(sm + SM_BH + nN * 80 + kk * 2) = hx; \
                *reinterpret_cast<__nv_bfloat16*>(sm + SM_BL + nN * 80 + kk * 2) = lx; \
                *reinterpret_cast<__nv_bfloat16*>(sm + SM_BH + (nN + 1) * 80 + kk * 2) = hy; \
                *reinterpret_cast<__nv_bfloat16*>(sm + SM_BL + (nN + 1) * 80 + kk * 2) = ly; \
            }                                                                    \
        }                                                                        \
    }

    PREFETCH(0);
    STAGE(0);
    __syncthreads();

    for (int c = 0; c < nChunks; c++) {
        if (c + 1 < nChunks) PREFETCH(c + 1);

        // ---- compute on buffer c&1: 2 k-steps of 16
        const uint32_t sb = sb0 + (uint32_t)((c & 1) * SM_BUF);
#pragma unroll
        for (int ks = 0; ks < 2; ks++) {
            uint32_t bh[4][2], bl[4][2];
#pragma unroll
            for (int ni = 0; ni < 4; ni++) {
                uint32_t off = (uint32_t)((wn * 32 + ni * 8 + (lane & 7)) * 80 + ks * 32 +
                                          ((lane >> 3) & 1) * 16);
                ldm_x2(bh[ni], sb + SM_BH + off);
                ldm_x2(bl[ni], sb + SM_BL + off);
            }
#pragma unroll
            for (int mi = 0; mi < 4; mi++) {
                uint32_t ah[4], al[4];
                uint32_t off = (uint32_t)((wm * 64 + mi * 16 + (lane & 15)) * 80 + ks * 32 +
                                          (lane >> 4) * 16);
                ldm_x4(ah, sb + SM_AH + off);
                ldm_x4(al, sb + SM_AL + off);
#pragma unroll
                for (int ni = 0; ni < 4; ni++) {
                    mma16816(acc[mi][ni], ah, bh[ni]);
                    mma16816(acc[mi][ni], ah, bl[ni]);
                    mma16816(acc[mi][ni], al, bh[ni]);
                }
            }
        }
        if (c + 1 < nChunks) STAGE((c + 1) & 1);
        __syncthreads();
    }
#undef PREFETCH
#undef STAGE

    // ---- epilogue: direct stores with relu / multiplicative mask
    const float* mR = g_scratch + offMaskR + (long)b * Sn;
    const float* mC = g_scratch + offMaskC + (long)b * Sn;
    const int trow = lane >> 2, tcol = (lane & 3) * 2;
#pragma unroll
    for (int mi = 0; mi < 4; mi++) {
        int r0 = m0 + wm * 64 + mi * 16 + trow;
        float rm0 = useMask ? mR[r0 - m0 + 0] : 1.0f;  // masks only when M==Sn
        float rm1 = useMask ? mR[r0 - m0 + 8] : 1.0f;
#pragma unroll
        for (int ni = 0; ni < 4; ni++) {
            int c0 = n0 + wn * 32 + ni * 8 + tcol;
            if (c0 >= Nreal) continue;
            float cm0 = useMask ? mC[c0] : 1.0f;
            float cm1 = useMask ? mC[c0 + 1] : 1.0f;
            float v0 = acc[mi][ni][0], v1 = acc[mi][ni][1];
            float v2 = acc[mi][ni][2], v3 = acc[mi][ni][3];
            if (doRelu) {
                v0 = fmaxf(v0, 0.f); v1 = fmaxf(v1, 0.f);
                v2 = fmaxf(v2, 0.f); v3 = fmaxf(v3, 0.f);
            }
            if (useMask) {
                v0 *= rm0 * cm0; v1 *= rm0 * cm1;
                v2 *= rm1 * cm0; v3 *= rm1 * cm1;
            }
            *reinterpret_cast<float2*>(C + (long)r0 * ldc + c0) = make_float2(v0, v1);
            *reinterpret_cast<float2*>(C + (long)(r0 + 8) * ldc + c0) = make_float2(v2, v3);
        }
    }
}

// ---------------------------------------------------------------------------
// All-weights transpose + bf16 split in ONE launch: W [K][N] -> [N][K] hi/lo
// ---------------------------------------------------------------------------
__global__ void k_wsplit_all(const float* __restrict__ w_intra,
                             const float* __restrict__ w_proj1,
                             const float* __restrict__ w_proj2,
                             const float* __restrict__ w_att,
                             const float* __restrict__ w_cmp1,
                             const float* __restrict__ w_cmp2) {
    const float* W;
    int K, N;
    long off;
    switch (blockIdx.y) {
        case 0: W = w_intra; K = En;     N = En;     off = WT_INTRA; break;
        case 1: W = w_proj1; K = 2 * En; N = Pn;     off = WT_PROJ1; break;
        case 2: W = w_proj2; K = 2 * En; N = Pn;     off = WT_PROJ2; break;
        case 3: W = w_att;   K = Pn;     N = Pn;     off = WT_ATT;   break;
        case 4: W = w_cmp1;  K = 2 * Pn; N = 2 * Pn; off = WT_CMP1;  break;
        default: W = w_cmp2; K = 2 * Pn; N = 2 * Pn; off = WT_CMP2;  break;
    }
    long total = (long)K * N;
    for (long i = (long)blockIdx.x * blockDim.x + threadIdx.x; i < total;
         i += (long)gridDim.x * blockDim.x) {
        int n = (int)(i / K), k = (int)(i % K);
        float v = W[(long)k * N + n];
        __nv_bfloat16 h, l;
        split1(v, h, l);
        g_wt[off + i] = h;
        g_wt[off + total + i] = l;
    }
}

// ---------------------------------------------------------------------------
// Non-GEMM kernels (validated R1/R3)
// ---------------------------------------------------------------------------
__global__ void k_seqmask(const int* __restrict__ x1, const int* __restrict__ x2) {
    int b = blockIdx.x;
    const int* x = blockIdx.y ? x2 : x1;
    float* m = g_scratch + (blockIdx.y ? OFF_MASK2 : OFF_MASK1);
    int t = threadIdx.x;
    int nz = __syncthreads_count(x[b * Sn + t] != 0);
    m[b * Sn + t] = (t < nz) ? 1.0f : 0.0f;
}

__global__ void k_gather(const int* __restrict__ x1, const int* __restrict__ x2,
                         const float* __restrict__ emb) {
    long bs = blockIdx.x;
    const int* x = blockIdx.y ? x2 : x1;
    float* cat = g_scratch + (blockIdx.y ? OFF_CAT2 : OFF_CAT1);
    int row = x[bs];
    const float* e = emb + (long)row * En;
    int t = threadIdx.x;
    float v[3];
    float ss = 0.f;
#pragma unroll
    for (int i = 0; i < 3; i++) {
        int idx = t + i * 128;
        v[i] = (idx < En) ? e[idx] : 0.f;
        ss += v[i] * v[i];
    }
    __shared__ float red[4];
#pragma unroll
    for (int o = 16; o; o >>= 1) ss += __shfl_xor_sync(0xffffffffu, ss, o);
    if ((t & 31) == 0) red[t >> 5] = ss;
    __syncthreads();
    float tot = red[0] + red[1] + red[2] + red[3];
    float inv = 1.0f / sqrtf(fmaxf(tot, 1e-12f));
    float* out = cat + bs * (2L * En);
#pragma unroll
    for (int i = 0; i < 3; i++) {
        int idx = t + i * 128;
        if (idx < En) out[idx] = v[i] * inv;
    }
}

__global__ void k_softmax_rows(long off, const float* __restrict__ biasPtr, int useDbias) {
    long bi = blockIdx.x;
    int i = (int)(bi % Sn);
    float* row = g_scratch + off + bi * Sn;
    int j = threadIdx.x;
    float v = row[j];
    if (useDbias) {
        int d = i - j; if (d < 0) d = -d;
        if (d >= 10) v += biasPtr[0];
    }
    __shared__ float shm[4];
    __shared__ float shs[4];
    float m = v;
#pragma unroll
    for (int o = 16; o; o >>= 1) m = fmaxf(m, __shfl_xor_sync(0xffffffffu, m, o));
    if ((j & 31) == 0) shm[j >> 5] = m;
    __syncthreads();
    m = fmaxf(fmaxf(shm[0], shm[1]), fmaxf(shm[2], shm[3]));
    float e = expf(v - m);
    float s = e;
#pragma unroll
    for (int o = 16; o; o >>= 1) s += __shfl_xor_sync(0xffffffffu, s, o);
    if ((j & 31) == 0) shs[j >> 5] = s;
    __syncthreads();
    s = shs[0] + shs[1] + shs[2] + shs[3];
    row[j] = e / s;
}

__global__ void k_softmax_colsT(long offSim, long offOut) {
    int b = blockIdx.x;
    int j0 = blockIdx.y * 32;
    __shared__ float sh[128][33];
    __shared__ float cmax[32], cinv[32];
    const float* sim = g_scratch + offSim + (long)b * Sn * Sn;
    float* outT = g_scratch + offOut + (long)b * Sn * Sn;
    int tid = threadIdx.x;
    for (int idx = tid; idx < 128 * 32; idx += 256) {
        int k = idx >> 5, j = idx & 31;
        sh[k][j] = sim[k * Sn + j0 + j];
    }
    __syncthreads();
    if (tid < 32) {
        float m = -1e30f;
        for (int k = 0; k < 128; k++) m = fmaxf(m, sh[k][tid]);
        float s = 0.f;
        for (int k = 0; k < 128; k++) s += expf(sh[k][tid] - m);
        cmax[tid] = m;
        cinv[tid] = 1.0f / s;
    }
    __syncthreads();
    for (int idx = tid; idx < 128 * 32; idx += 256) {
        int j = idx >> 7, k = idx & 127;
        outT[(long)(j0 + j) * Sn + k] = expf(sh[k][j] - cmax[j]) * cinv[j];
    }
}

__global__ void k_pool() {
    int b = blockIdx.x;
    __shared__ float m1[128], m2[128];
    int tid = threadIdx.x;
    if (tid < 128) {
        m1[tid] = g_scratch[OFF_MASK1 + (long)b * Sn + tid];
        m2[tid] = g_scratch[OFF_MASK2 + (long)b * Sn + tid];
    }
    __syncthreads();
    const float* v1 = g_scratch + OFF_V1 + (long)b * Sn * 400;
    const float* v2 = g_scratch + OFF_V2 + (long)b * Sn * 400;
    float* pool = g_scratch + OFF_POOL + (long)b * 800;
    for (int n = tid; n < 400; n += 256) {
        float s1 = 0.f, s2 = 0.f;
        for (int s = 0; s < 128; s++) {
            s1 += v1[(long)s * 400 + n] * m1[s];
            s2 += v2[(long)s * 400 + n] * m2[s];
        }
        pool[n] = s1;
        pool[400 + n] = s2;
    }
}

__global__ void k_final(const float* __restrict__ w_agg, float* __restrict__ out) {
    int b = blockIdx.x;
    int tid = threadIdx.x;
    int c = tid >> 5, lane = tid & 31;
    const float* p = g_scratch + OFF_POOL + (long)b * 800;
    float acc = 0.f;
    for (int n = lane; n < 800; n += 32) acc += p[n] * w_agg[n * Cn + c];
#pragma unroll
    for (int o = 16; o; o >>= 1) acc += __shfl_xor_sync(0xffffffffu, acc, o);
    if (lane == 0) out[b * Cn + c] = fmaxf(acc, 0.f);
}

// ---------------------------------------------------------------------------
// Orchestration — sides merged into single launches via batch strides
// ---------------------------------------------------------------------------
static inline void launch_gemm(long offA, int lda, long sA,
                               long wtOff, long wtStride,
                               long offB, int ldb, long sB, int bNmajor,
                               long offC, int ldc, long sC,
                               int M, int Nreal, int K,
                               int doRelu, int useMask, long offMaskR, long offMaskC,
                               int batch) {
    dim3 grid((Nreal + 127) / 128, M / 128, batch);
    k_hmma_gemm<<<grid, 256, SMEM_BYTES>>>(offA, lda, sA, wtOff, wtStride,
                                           offB, ldb, sB, bNmajor,
                                           offC, ldc, sC, Nreal, K,
                                           doRelu, useMask, offMaskR, offMaskC);
}

extern "C" void kernel_launch(void* const* d_in, const int* in_sizes, int n_in,
                              void* d_out, int out_size) {
    const int* x1 = (const int*)d_in[0];
    const int* x2 = (const int*)d_in[1];
    const float* emb = (const float*)d_in[2];
    const float* w_intra = (const float*)d_in[3];
    const float* bias_intra = (const float*)d_in[4];
    const float* w_proj1 = (const float*)d_in[5];
    const float* w_proj2 = (const float*)d_in[6];
    const float* w_att = (const float*)d_in[7];
    const float* w_cmp1 = (const float*)d_in[8];
    const float* w_cmp2 = (const float*)d_in[9];
    const float* w_agg = (const float*)d_in[10];
    float* out = (float*)d_out;

    cudaFuncSetAttribute(k_hmma_gemm, cudaFuncAttributeMaxDynamicSharedMemorySize, SMEM_BYTES);

    k_seqmask<<<dim3(Bn, 2), Sn>>>(x1, x2);
    k_gather<<<dim3((unsigned)BS, 2), 128>>>(x1, x2, emb);
    k_wsplit_all<<<dim3(160, 6), 256>>>(w_intra, w_proj1, w_proj2, w_att, w_cmp1, w_cmp2);

    // f = relu(e @ w_intra), BOTH sides: [2 x 32768 x 300], K=300
    launch_gemm(OFF_CAT1, 2 * En, BS * 2 * En, WT_INTRA, 0, 0, 0, 0, 0,
                OFF_F, En, BS * En, (int)BS, En, En, 1, 0, 0, 0, 2);

    // att[g] = f[g] @ f[g]^T, 512 batches (both sides): [128x128], K=300
    launch_gemm(OFF_F, En, (long)Sn * En, -1, 0,
                OFF_F, En, (long)Sn * En, 0,
                OFF_ATT, Sn, (long)Sn * Sn, Sn, Sn, En, 0, 0, 0, 0, 2 * Bn);

    k_softmax_rows<<<(unsigned)(2 * BS), Sn>>>(OFF_ATT, bias_intra, 1);

    // xp[g] = att[g] @ e[g]: [128 x 300], K=128 (B N-major) -> cat[:,300:600]
    launch_gemm(OFF_ATT, Sn, (long)Sn * Sn, -1, 0,
                OFF_CAT1, 2 * En, (long)Sn * 2 * En, 1,
                OFF_CAT1 + En, 2 * En, (long)Sn * 2 * En, Sn, En, Sn, 0, 0, 0, 0, 2 * Bn);

    // x_proj = relu(cat @ w_proj{1,2}): [2 x 32768 x 200], K=600
    launch_gemm(OFF_CAT1, 2 * En, BS * 2 * En, WT_PROJ1, WT_PROJ2 - WT_PROJ1, 0, 0, 0, 0,
                OFF_CAT1P, 2 * Pn, BS * 2 * Pn, (int)BS, Pn, 2 * En, 1, 0, 0, 0, 2);

    // fa = relu(x_proj @ w_att): [2 x 32768 x 200], K=200
    launch_gemm(OFF_CAT1P, 2 * Pn, BS * 2 * Pn, WT_ATT, 0, 0, 0, 0, 0,
                OFF_FA1, Pn, BS * Pn, (int)BS, Pn, Pn, 1, 0, 0, 0, 2);

    // sim[b] = fa1[b] @ fa2[b]^T, multiplicative mask epilogue
    launch_gemm(OFF_FA1, Pn, (long)Sn * Pn, -1, 0,
                OFF_FA2, Pn, (long)Sn * Pn, 0,
                OFF_SIM, Sn, (long)Sn * Sn, Sn, Sn, Pn, 0, 1, OFF_MASK1, OFF_MASK2, Bn);

    k_softmax_colsT<<<dim3(Bn, 4), 256>>>(OFF_SIM, OFF_SMT);
    k_softmax_rows<<<(unsigned)BS, Sn>>>(OFF_SIM, nullptr, 0);

    // beta[b] = sm2[b] @ x2p[b]: [128 x 200], K=128 -> cat1p[:,200:400]
    launch_gemm(OFF_SIM, Sn, (long)Sn * Sn, -1, 0,
                OFF_CAT2P, 2 * Pn, (long)Sn * 2 * Pn, 1,
                OFF_CAT1P + Pn, 2 * Pn, (long)Sn * 2 * Pn, Sn, Pn, Sn, 0, 0, 0, 0, Bn);

    // alpha[b] = smT[b] @ x1p[b] -> cat2p[:,200:400]
    launch_gemm(OFF_SMT, Sn, (long)Sn * Sn, -1, 0,
                OFF_CAT1P, 2 * Pn, (long)Sn * 2 * Pn, 1,
                OFF_CAT2P + Pn, 2 * Pn, (long)Sn * 2 * Pn, Sn, Pn, Sn, 0, 0, 0, 0, Bn);

    // v = relu([xp|attend] @ w_cmp{1,2}): [2 x 32768 x 400], K=400
    launch_gemm(OFF_CAT1P, 2 * Pn, BS * 2 * Pn, WT_CMP1, WT_CMP2 - WT_CMP1, 0, 0, 0, 0,
                OFF_V1, 2 * Pn, BS * 2 * Pn, (int)BS, 2 * Pn, 2 * Pn, 1, 0, 0, 0, 2);

    k_pool<<<Bn, 256>>>();
    k_final<<<Bn, 96>>>(w_agg, out);
}